// round 6
// baseline (speedup 1.0000x reference)
#include <cuda_runtime.h>
#include <cstdint>

// Problem dims (fixed by the reference).
#define L_DIM 8192
#define B_DIM 4096
#define D_DIM 1024

// Global accumulators / scratch (no allocation allowed).
__device__ double g_local_sum;
__device__ double g_glob_sum;
__device__ float  g_pos[B_DIM];

// ---------------------------------------------------------------------------
// f32x2 packed helpers (sm_100+ PTX; ptxas will not emit FFMA2 from C++)
// ---------------------------------------------------------------------------
__device__ __forceinline__ uint64_t pack2(float x) {
    uint32_t xi = __float_as_uint(x);
    uint64_t r;
    asm("mov.b64 %0, {%1, %1};" : "=l"(r) : "r"(xi));
    return r;
}

__device__ __forceinline__ void ffma2(uint64_t& c, uint64_t a, uint64_t b) {
    asm("fma.rn.f32x2 %0, %1, %2, %0;" : "+l"(c) : "l"(a), "l"(b));
}

__device__ __forceinline__ float lo32(uint64_t v) {
    return __uint_as_float((uint32_t)(v & 0xffffffffull));
}
__device__ __forceinline__ float hi32(uint64_t v) {
    return __uint_as_float((uint32_t)(v >> 32));
}

// ---------------------------------------------------------------------------
// init: zero the scalar accumulators (every launch; graph-deterministic)
// ---------------------------------------------------------------------------
__global__ void init_kernel() {
    g_local_sum = 0.0;
    g_glob_sum  = 0.0;
}

// ---------------------------------------------------------------------------
// local loss: sum(q_hat * q_real) over 8.4M elements (HBM-bound)
// ---------------------------------------------------------------------------
__global__ void local_kernel(const float* __restrict__ qh,
                             const float* __restrict__ qr) {
    const size_t n4 = (size_t)L_DIM * D_DIM / 4;
    const float4* a4 = (const float4*)qh;
    const float4* b4 = (const float4*)qr;

    float s = 0.0f;
    for (size_t idx = (size_t)blockIdx.x * blockDim.x + threadIdx.x;
         idx < n4; idx += (size_t)gridDim.x * blockDim.x) {
        float4 a = a4[idx];
        float4 b = b4[idx];
        s += a.x * b.x + a.y * b.y + a.z * b.z + a.w * b.w;
    }

    // warp reduce (float is fine per-warp; promote to double per-block)
    for (int o = 16; o > 0; o >>= 1) s += __shfl_down_sync(0xffffffffu, s, o);

    __shared__ double red[8];
    int t = threadIdx.x;
    if ((t & 31) == 0) red[t >> 5] = (double)s;
    __syncthreads();
    if (t == 0) {
        double tot = 0.0;
        #pragma unroll
        for (int w = 0; w < 8; w++) tot += red[w];
        atomicAdd(&g_local_sum, tot);
    }
}

// ---------------------------------------------------------------------------
// pos: g_pos[i] = dot(pred[i], gt[i]) ; one block (256 thr) per row, D=1024
// ---------------------------------------------------------------------------
__global__ void pos_kernel(const float* __restrict__ pred,
                           const float* __restrict__ gt) {
    int i = blockIdx.x;
    int t = threadIdx.x;  // 0..255, D/4 = 256 float4 per row
    const float4* p4 = (const float4*)(pred + (size_t)i * D_DIM);
    const float4* g4 = (const float4*)(gt   + (size_t)i * D_DIM);
    float4 a = p4[t];
    float4 b = g4[t];
    float s = a.x * b.x + a.y * b.y + a.z * b.z + a.w * b.w;

    for (int o = 16; o > 0; o >>= 1) s += __shfl_down_sync(0xffffffffu, s, o);

    __shared__ float red[8];
    if ((t & 31) == 0) red[t >> 5] = s;
    __syncthreads();
    if (t == 0) {
        float tot = 0.0f;
        #pragma unroll
        for (int w = 0; w < 8; w++) tot += red[w];
        g_pos[i] = tot;
    }
}

// ---------------------------------------------------------------------------
// Fused NT-GEMM (scores = pred @ gt^T) + hinge + global reduce.
// 128x128 tile, BK=16, 256 threads, 8x8 micro-tile, f32x2 packed accumulators.
// ---------------------------------------------------------------------------
#define BK   16
#define SSTR 132   // smem row stride (floats): 2-way STS conflicts, 16B-aligned rows

__global__ __launch_bounds__(256, 2)
void gemm_hinge_kernel(const float* __restrict__ pred,
                       const float* __restrict__ gt) {
    __shared__ __align__(16) float As[BK * SSTR];
    __shared__ __align__(16) float Bs[BK * SSTR];
    __shared__ double redsm[8];

    const int t  = threadIdx.x;
    const int tc = t & 15;   // 16 col-groups
    const int tr = t >> 4;   // 16 row-groups
    const int rowA0 = blockIdx.y * 128;  // pred rows (i)
    const int rowB0 = blockIdx.x * 128;  // gt rows   (j)

    // Loader mapping: 512 float4 per operand tile, 2 per thread.
    const int ra0 = t >> 2;             // rows 0..63
    const int kq0 = t & 3;              // float4 within the 16-wide k slab
    const int ra1 = (t + 256) >> 2;     // rows 64..127
    const int kq1 = kq0;

    const float4* A4 = (const float4*)pred;  // row stride 256 float4
    const float4* B4 = (const float4*)gt;

    uint64_t c2[8][4];
    #pragma unroll
    for (int i = 0; i < 8; i++)
        #pragma unroll
        for (int p = 0; p < 4; p++) c2[i][p] = 0ull;

    for (int k0 = 0; k0 < D_DIM; k0 += BK) {
        const int kc4 = k0 >> 2;
        float4 va0 = A4[(size_t)(rowA0 + ra0) * 256 + kc4 + kq0];
        float4 va1 = A4[(size_t)(rowA0 + ra1) * 256 + kc4 + kq1];
        float4 vb0 = B4[(size_t)(rowB0 + ra0) * 256 + kc4 + kq0];
        float4 vb1 = B4[(size_t)(rowB0 + ra1) * 256 + kc4 + kq1];

        __syncthreads();  // previous iteration's reads complete

        {
            int kb = kq0 * 4;
            As[(kb + 0) * SSTR + ra0] = va0.x;
            As[(kb + 1) * SSTR + ra0] = va0.y;
            As[(kb + 2) * SSTR + ra0] = va0.z;
            As[(kb + 3) * SSTR + ra0] = va0.w;
            As[(kb + 0) * SSTR + ra1] = va1.x;
            As[(kb + 1) * SSTR + ra1] = va1.y;
            As[(kb + 2) * SSTR + ra1] = va1.z;
            As[(kb + 3) * SSTR + ra1] = va1.w;
            Bs[(kb + 0) * SSTR + ra0] = vb0.x;
            Bs[(kb + 1) * SSTR + ra0] = vb0.y;
            Bs[(kb + 2) * SSTR + ra0] = vb0.z;
            Bs[(kb + 3) * SSTR + ra0] = vb0.w;
            Bs[(kb + 0) * SSTR + ra1] = vb1.x;
            Bs[(kb + 1) * SSTR + ra1] = vb1.y;
            Bs[(kb + 2) * SSTR + ra1] = vb1.z;
            Bs[(kb + 3) * SSTR + ra1] = vb1.w;
        }
        __syncthreads();

        #pragma unroll
        for (int k = 0; k < BK; k++) {
            const float* as = &As[k * SSTR];
            const float* bs = &Bs[k * SSTR];
            float4 a0 = *(const float4*)(as + tr * 4);        // broadcast
            float4 a1 = *(const float4*)(as + 64 + tr * 4);   // broadcast
            uint64_t b0 = *(const uint64_t*)(bs + tc * 4);
            uint64_t b1 = *(const uint64_t*)(bs + tc * 4 + 2);
            uint64_t b2 = *(const uint64_t*)(bs + 64 + tc * 4);
            uint64_t b3 = *(const uint64_t*)(bs + 64 + tc * 4 + 2);
            float av[8] = {a0.x, a0.y, a0.z, a0.w, a1.x, a1.y, a1.z, a1.w};
            #pragma unroll
            for (int i = 0; i < 8; i++) {
                uint64_t ap = pack2(av[i]);
                ffma2(c2[i][0], ap, b0);
                ffma2(c2[i][1], ap, b1);
                ffma2(c2[i][2], ap, b2);
                ffma2(c2[i][3], ap, b3);
            }
        }
    }

    // Hinge epilogue: v = max(0, score - pos[i] + 1), accumulate in double.
    double acc = 0.0;
    #pragma unroll
    for (int i = 0; i < 8; i++) {
        int grow = rowA0 + ((i < 4) ? (tr * 4 + i) : (64 + tr * 4 + (i - 4)));
        float pm1 = 1.0f - g_pos[grow];  // (+1 - pos) folded
        #pragma unroll
        for (int p = 0; p < 4; p++) {
            float v0 = lo32(c2[i][p]) + pm1;
            float v1 = hi32(c2[i][p]) + pm1;
            if (v0 > 0.0f) acc += (double)v0;
            if (v1 > 0.0f) acc += (double)v1;
        }
    }

    for (int o = 16; o > 0; o >>= 1)
        acc += __shfl_down_sync(0xffffffffu, acc, o);
    if ((t & 31) == 0) redsm[t >> 5] = acc;
    __syncthreads();
    if (t == 0) {
        double tot = 0.0;
        #pragma unroll
        for (int w = 0; w < 8; w++) tot += redsm[w];
        atomicAdd(&g_glob_sum, tot);
    }
}

// ---------------------------------------------------------------------------
// finalize: out = glob - local_sum / L
// ---------------------------------------------------------------------------
__global__ void finalize_kernel(float* __restrict__ out) {
    out[0] = (float)(g_glob_sum - g_local_sum / (double)L_DIM);
}

// ---------------------------------------------------------------------------
extern "C" void kernel_launch(void* const* d_in, const int* in_sizes, int n_in,
                              void* d_out, int out_size) {
    (void)in_sizes; (void)n_in; (void)out_size;
    const float* q_hat  = (const float*)d_in[0];
    const float* q_real = (const float*)d_in[1];
    const float* gt     = (const float*)d_in[2];  // encoded_gt   [B, D]
    const float* pred   = (const float*)d_in[3];  // encoded_pred [B, D]
    float* out = (float*)d_out;

    init_kernel<<<1, 1>>>();
    local_kernel<<<2048, 256>>>(q_hat, q_real);
    pos_kernel<<<B_DIM, 256>>>(pred, gt);
    dim3 grid(B_DIM / 128, B_DIM / 128);  // (j-tiles, i-tiles)
    gemm_hinge_kernel<<<grid, 256>>>(pred, gt);
    finalize_kernel<<<1, 1>>>(out);
}

// round 8
// speedup vs baseline: 2.2312x; 2.2312x over previous
#include <cuda_runtime.h>
#include <cstdint>

// Problem dims (fixed by the reference).
#define L_DIM 8192
#define B_DIM 4096
#define D_DIM 1024

// Global accumulators / scratch (no allocation allowed).
__device__ double g_local_sum;
__device__ double g_glob_sum;
__device__ float  g_pos[B_DIM];

// ---------------------------------------------------------------------------
// PTX helpers
// ---------------------------------------------------------------------------
__device__ __forceinline__ uint32_t smem_u32(const void* p) {
    uint32_t a;
    asm("{ .reg .u64 t; cvta.to.shared.u64 t, %1; cvt.u32.u64 %0, t; }"
        : "=r"(a) : "l"(p));
    return a;
}

__device__ __forceinline__ void cp_async16(uint32_t dst, const void* src) {
    asm volatile("cp.async.cg.shared.global [%0], [%1], 16;"
                 :: "r"(dst), "l"(src) : "memory");
}
__device__ __forceinline__ void cp_commit() {
    asm volatile("cp.async.commit_group;" ::: "memory");
}
__device__ __forceinline__ void cp_wait1() {
    asm volatile("cp.async.wait_group 1;" ::: "memory");
}
__device__ __forceinline__ void cp_wait0() {
    asm volatile("cp.async.wait_group 0;" ::: "memory");
}

__device__ __forceinline__ uint32_t lds32(uint32_t addr) {
    uint32_t v;
    asm volatile("ld.shared.b32 %0, [%1];" : "=r"(v) : "r"(addr));
    return v;
}

// m16n8k8 tf32 MMA (baseline PTX, legacy-HMMA path on sm_103).
__device__ __forceinline__ void mma_tf32(float* c, const uint32_t* a,
                                         const uint32_t* b) {
    asm volatile(
        "mma.sync.aligned.m16n8k8.row.col.f32.tf32.tf32.f32 "
        "{%0,%1,%2,%3}, {%4,%5,%6,%7}, {%8,%9}, {%0,%1,%2,%3};"
        : "+f"(c[0]), "+f"(c[1]), "+f"(c[2]), "+f"(c[3])
        : "r"(a[0]), "r"(a[1]), "r"(a[2]), "r"(a[3]), "r"(b[0]), "r"(b[1]));
}

// ---------------------------------------------------------------------------
// init / local / pos / finalize
// ---------------------------------------------------------------------------
__global__ void init_kernel() {
    g_local_sum = 0.0;
    g_glob_sum  = 0.0;
}

__global__ void local_kernel(const float* __restrict__ qh,
                             const float* __restrict__ qr) {
    const size_t n4 = (size_t)L_DIM * D_DIM / 4;
    const float4* a4 = (const float4*)qh;
    const float4* b4 = (const float4*)qr;

    float s = 0.0f;
    for (size_t idx = (size_t)blockIdx.x * blockDim.x + threadIdx.x;
         idx < n4; idx += (size_t)gridDim.x * blockDim.x) {
        float4 a = a4[idx];
        float4 b = b4[idx];
        s += a.x * b.x + a.y * b.y + a.z * b.z + a.w * b.w;
    }
    for (int o = 16; o > 0; o >>= 1) s += __shfl_down_sync(0xffffffffu, s, o);

    __shared__ double red[8];
    int t = threadIdx.x;
    if ((t & 31) == 0) red[t >> 5] = (double)s;
    __syncthreads();
    if (t == 0) {
        double tot = 0.0;
        #pragma unroll
        for (int w = 0; w < 8; w++) tot += red[w];
        atomicAdd(&g_local_sum, tot);
    }
}

__global__ void pos_kernel(const float* __restrict__ pred,
                           const float* __restrict__ gt) {
    int i = blockIdx.x;
    int t = threadIdx.x;
    const float4* p4 = (const float4*)(pred + (size_t)i * D_DIM);
    const float4* g4 = (const float4*)(gt   + (size_t)i * D_DIM);
    float4 a = p4[t];
    float4 b = g4[t];
    float s = a.x * b.x + a.y * b.y + a.z * b.z + a.w * b.w;

    for (int o = 16; o > 0; o >>= 1) s += __shfl_down_sync(0xffffffffu, s, o);

    __shared__ float red[8];
    if ((t & 31) == 0) red[t >> 5] = s;
    __syncthreads();
    if (t == 0) {
        float tot = 0.0f;
        #pragma unroll
        for (int w = 0; w < 8; w++) tot += red[w];
        g_pos[i] = tot;
    }
}

// ---------------------------------------------------------------------------
// mma.sync tf32 NT-GEMM (scores = pred @ gt^T) + hinge + global reduce.
// CTA tile 128(i) x 256(j), BK=32 floats (128B rows, XOR-16B swizzle),
// 8 warps in 2x4 grid, 64x64 warp tile, 2-stage cp.async pipeline.
// ---------------------------------------------------------------------------
#define TM 128
#define TN 256
#define BKF 32
#define STAGE_A_BYTES (TM * 128)               // 16 KB
#define STAGE_B_BYTES (TN * 128)               // 32 KB
#define STAGE_BYTES   (STAGE_A_BYTES + STAGE_B_BYTES)
#define DYN_SMEM (2 * STAGE_BYTES + 1024)
#define NKITERS (D_DIM / BKF)                  // 32

__device__ __forceinline__ void load_stage(uint32_t aBase, uint32_t bBase,
                                           const float* __restrict__ pred,
                                           const float* __restrict__ gt,
                                           int rowA0, int rowB0, int k0, int t) {
    // A: 128 rows x 8 chunks(16B) = 1024 chunks, 4/thread
    #pragma unroll
    for (int q = 0; q < 4; q++) {
        int idx = t + 256 * q;
        int row = idx >> 3;
        int c   = idx & 7;
        const float* src = pred + (size_t)(rowA0 + row) * D_DIM + k0 + c * 4;
        uint32_t dst = aBase + row * 128 + ((c ^ (row & 7)) << 4);
        cp_async16(dst, src);
    }
    // B: 256 rows x 8 chunks = 2048 chunks, 8/thread
    #pragma unroll
    for (int q = 0; q < 8; q++) {
        int idx = t + 256 * q;
        int row = idx >> 3;
        int c   = idx & 7;
        const float* src = gt + (size_t)(rowB0 + row) * D_DIM + k0 + c * 4;
        uint32_t dst = bBase + row * 128 + ((c ^ (row & 7)) << 4);
        cp_async16(dst, src);
    }
}

__global__ __launch_bounds__(256)
void gemm_hinge_mma(const float* __restrict__ pred, const float* __restrict__ gt) {
    extern __shared__ char dyn[];
    __shared__ double redsm[8];

    const int t    = threadIdx.x;
    const int wid  = t >> 5;
    const int lane = t & 31;
    const int wm   = wid & 1;    // warp row (2)
    const int wn   = wid >> 1;   // warp col (4)
    const int tg   = lane >> 2;  // groupID 0..7
    const int ti   = lane & 3;   // thread-in-group 0..3
    const int rowA0 = blockIdx.y * TM;   // pred rows (i)
    const int rowB0 = blockIdx.x * TN;   // gt rows   (j)

    const uint32_t dyn_base = (smem_u32(dyn) + 1023u) & ~1023u;

    float c[4][8][4];
    #pragma unroll
    for (int mf = 0; mf < 4; mf++)
        #pragma unroll
        for (int nf = 0; nf < 8; nf++)
            #pragma unroll
            for (int r = 0; r < 4; r++) c[mf][nf][r] = 0.0f;

    // Prologue: prefetch stages 0, 1.
    load_stage(dyn_base,               dyn_base + STAGE_A_BYTES,
               pred, gt, rowA0, rowB0, 0, t);
    cp_commit();
    load_stage(dyn_base + STAGE_BYTES, dyn_base + STAGE_BYTES + STAGE_A_BYTES,
               pred, gt, rowA0, rowB0, BKF, t);
    cp_commit();

    for (int it = 0; it < NKITERS; ++it) {
        const uint32_t aBase = dyn_base + (it & 1) * STAGE_BYTES;
        const uint32_t bBase = aBase + STAGE_A_BYTES;

        if (it == NKITERS - 1) cp_wait0(); else cp_wait1();
        __syncthreads();

        #pragma unroll
        for (int ks = 0; ks < 4; ks++) {
            const int ch0 = ks * 2;      // 16B-chunk of k = ks*8 + ti
            const int ch1 = ks * 2 + 1;  // 16B-chunk of k = ks*8 + 4 + ti

            uint32_t a[4][4];
            #pragma unroll
            for (int mf = 0; mf < 4; mf++) {
                int r0 = wm * 64 + mf * 16 + tg;
                int r1 = r0 + 8;
                a[mf][0] = lds32(aBase + r0 * 128 + ((ch0 ^ (r0 & 7)) << 4) + ti * 4);
                a[mf][1] = lds32(aBase + r1 * 128 + ((ch0 ^ (r1 & 7)) << 4) + ti * 4);
                a[mf][2] = lds32(aBase + r0 * 128 + ((ch1 ^ (r0 & 7)) << 4) + ti * 4);
                a[mf][3] = lds32(aBase + r1 * 128 + ((ch1 ^ (r1 & 7)) << 4) + ti * 4);
            }
            uint32_t b[8][2];
            #pragma unroll
            for (int nf = 0; nf < 8; nf++) {
                int n = wn * 64 + nf * 8 + tg;
                b[nf][0] = lds32(bBase + n * 128 + ((ch0 ^ (n & 7)) << 4) + ti * 4);
                b[nf][1] = lds32(bBase + n * 128 + ((ch1 ^ (n & 7)) << 4) + ti * 4);
            }
            #pragma unroll
            for (int mf = 0; mf < 4; mf++)
                #pragma unroll
                for (int nf = 0; nf < 8; nf++)
                    mma_tf32(c[mf][nf], a[mf], b[nf]);
        }

        if (it + 2 < NKITERS) {
            __syncthreads();  // all warps done reading stage before overwrite
            load_stage(aBase, bBase, pred, gt, rowA0, rowB0, (it + 2) * BKF, t);
            cp_commit();
        }
    }

    // Hinge epilogue straight from register accumulators.
    // c[mf][nf][{0,1}] -> row r0 = wm*64+mf*16+tg, cols j0, j0+1
    // c[mf][nf][{2,3}] -> row r1 = r0 + 8,         cols j0, j0+1
    double acc = 0.0;
    #pragma unroll
    for (int mf = 0; mf < 4; mf++) {
        int r0 = rowA0 + wm * 64 + mf * 16 + tg;
        float p0 = 1.0f - g_pos[r0];
        float p1 = 1.0f - g_pos[r0 + 8];
        #pragma unroll
        for (int nf = 0; nf < 8; nf++) {
            float v0 = c[mf][nf][0] + p0;
            float v1 = c[mf][nf][1] + p0;
            float v2 = c[mf][nf][2] + p1;
            float v3 = c[mf][nf][3] + p1;
            if (v0 > 0.0f) acc += (double)v0;
            if (v1 > 0.0f) acc += (double)v1;
            if (v2 > 0.0f) acc += (double)v2;
            if (v3 > 0.0f) acc += (double)v3;
        }
    }

    for (int o = 16; o > 0; o >>= 1)
        acc += __shfl_down_sync(0xffffffffu, acc, o);
    if (lane == 0) redsm[wid] = acc;
    __syncthreads();
    if (t == 0) {
        double tot = 0.0;
        #pragma unroll
        for (int w = 0; w < 8; w++) tot += redsm[w];
        atomicAdd(&g_glob_sum, tot);
    }
}

// ---------------------------------------------------------------------------
__global__ void finalize_kernel(float* __restrict__ out) {
    out[0] = (float)(g_glob_sum - g_local_sum / (double)L_DIM);
}

// ---------------------------------------------------------------------------
extern "C" void kernel_launch(void* const* d_in, const int* in_sizes, int n_in,
                              void* d_out, int out_size) {
    (void)in_sizes; (void)n_in; (void)out_size;
    const float* q_hat  = (const float*)d_in[0];
    const float* q_real = (const float*)d_in[1];
    const float* gt     = (const float*)d_in[2];  // encoded_gt   [B, D]
    const float* pred   = (const float*)d_in[3];  // encoded_pred [B, D]
    float* out = (float*)d_out;

    cudaFuncSetAttribute(gemm_hinge_mma,
                         cudaFuncAttributeMaxDynamicSharedMemorySize, DYN_SMEM);

    init_kernel<<<1, 1>>>();
    local_kernel<<<2048, 256>>>(q_hat, q_real);
    pos_kernel<<<B_DIM, 256>>>(pred, gt);
    dim3 grid(B_DIM / TN, B_DIM / TM);  // (16 j-tiles, 32 i-tiles)
    gemm_hinge_mma<<<grid, 256, DYN_SMEM>>>(pred, gt);
    finalize_kernel<<<1, 1>>>(out);
}

// round 9
// speedup vs baseline: 2.2468x; 1.0070x over previous
#include <cuda_runtime.h>
#include <cstdint>

// Problem dims (fixed by the reference).
#define L_DIM 8192
#define B_DIM 4096
#define D_DIM 1024

// Global accumulators / scratch (no allocation allowed).
__device__ double g_local_sum;
__device__ double g_glob_sum;
__device__ float  g_pos[B_DIM];

// ---------------------------------------------------------------------------
// PTX helpers
// ---------------------------------------------------------------------------
__device__ __forceinline__ uint32_t smem_u32(const void* p) {
    uint32_t a;
    asm("{ .reg .u64 t; cvta.to.shared.u64 t, %1; cvt.u32.u64 %0, t; }"
        : "=r"(a) : "l"(p));
    return a;
}

__device__ __forceinline__ void cp_async16(uint32_t dst, const void* src) {
    asm volatile("cp.async.cg.shared.global [%0], [%1], 16;"
                 :: "r"(dst), "l"(src) : "memory");
}
__device__ __forceinline__ void cp_commit() {
    asm volatile("cp.async.commit_group;" ::: "memory");
}
__device__ __forceinline__ void cp_wait1() {
    asm volatile("cp.async.wait_group 1;" ::: "memory");
}
__device__ __forceinline__ void cp_wait0() {
    asm volatile("cp.async.wait_group 0;" ::: "memory");
}

// ldmatrix x4: four 8x16B tiles -> 4 regs/thread. For f32 data this delivers
// the tf32 m16n8k8 fragment ownership pattern directly (thread ln -> row ln/4,
// f32 col ln%4 of each 8x4-float tile).
__device__ __forceinline__ void ldsm4(uint32_t* r, uint32_t addr) {
    asm volatile("ldmatrix.sync.aligned.m8n8.x4.shared.b16 {%0,%1,%2,%3}, [%4];"
                 : "=r"(r[0]), "=r"(r[1]), "=r"(r[2]), "=r"(r[3]) : "r"(addr));
}

// m16n8k8 tf32 MMA (baseline PTX, legacy-HMMA path on sm_103).
__device__ __forceinline__ void mma_tf32(float* c, const uint32_t* a,
                                         const uint32_t* b) {
    asm volatile(
        "mma.sync.aligned.m16n8k8.row.col.f32.tf32.tf32.f32 "
        "{%0,%1,%2,%3}, {%4,%5,%6,%7}, {%8,%9}, {%0,%1,%2,%3};"
        : "+f"(c[0]), "+f"(c[1]), "+f"(c[2]), "+f"(c[3])
        : "r"(a[0]), "r"(a[1]), "r"(a[2]), "r"(a[3]), "r"(b[0]), "r"(b[1]));
}

// ---------------------------------------------------------------------------
// init / local / pos / finalize
// ---------------------------------------------------------------------------
__global__ void init_kernel() {
    g_local_sum = 0.0;
    g_glob_sum  = 0.0;
}

__global__ void local_kernel(const float* __restrict__ qh,
                             const float* __restrict__ qr) {
    const size_t n4 = (size_t)L_DIM * D_DIM / 4;
    const float4* a4 = (const float4*)qh;
    const float4* b4 = (const float4*)qr;

    float s = 0.0f;
    for (size_t idx = (size_t)blockIdx.x * blockDim.x + threadIdx.x;
         idx < n4; idx += (size_t)gridDim.x * blockDim.x) {
        float4 a = a4[idx];
        float4 b = b4[idx];
        s += a.x * b.x + a.y * b.y + a.z * b.z + a.w * b.w;
    }
    for (int o = 16; o > 0; o >>= 1) s += __shfl_down_sync(0xffffffffu, s, o);

    __shared__ double red[8];
    int t = threadIdx.x;
    if ((t & 31) == 0) red[t >> 5] = (double)s;
    __syncthreads();
    if (t == 0) {
        double tot = 0.0;
        #pragma unroll
        for (int w = 0; w < 8; w++) tot += red[w];
        atomicAdd(&g_local_sum, tot);
    }
}

__global__ void pos_kernel(const float* __restrict__ pred,
                           const float* __restrict__ gt) {
    int i = blockIdx.x;
    int t = threadIdx.x;
    const float4* p4 = (const float4*)(pred + (size_t)i * D_DIM);
    const float4* g4 = (const float4*)(gt   + (size_t)i * D_DIM);
    float4 a = p4[t];
    float4 b = g4[t];
    float s = a.x * b.x + a.y * b.y + a.z * b.z + a.w * b.w;

    for (int o = 16; o > 0; o >>= 1) s += __shfl_down_sync(0xffffffffu, s, o);

    __shared__ float red[8];
    if ((t & 31) == 0) red[t >> 5] = s;
    __syncthreads();
    if (t == 0) {
        float tot = 0.0f;
        #pragma unroll
        for (int w = 0; w < 8; w++) tot += red[w];
        g_pos[i] = tot;
    }
}

// ---------------------------------------------------------------------------
// mma.sync tf32 NT-GEMM (scores = pred @ gt^T) + hinge + global reduce.
// CTA 128(i) x 256(j), BK=32 floats (128B rows, XOR-16B swizzle),
// 8 warps 2x4 (64x64 warp tile), 3-stage cp.async pipeline, ldmatrix feeds.
// ---------------------------------------------------------------------------
#define TM 128
#define TN 256
#define BKF 32
#define STAGE_A_BYTES (TM * 128)               // 16 KB
#define STAGE_B_BYTES (TN * 128)               // 32 KB
#define STAGE_BYTES   (STAGE_A_BYTES + STAGE_B_BYTES)
#define NSTAGE 3
#define DYN_SMEM (NSTAGE * STAGE_BYTES + 1024)
#define NKITERS (D_DIM / BKF)                  // 32

__device__ __forceinline__ void load_stage(uint32_t aBase, uint32_t bBase,
                                           const float* __restrict__ pred,
                                           const float* __restrict__ gt,
                                           int rowA0, int rowB0, int k0, int t) {
    // A: 128 rows x 8 chunks(16B) = 1024 chunks, 4/thread
    #pragma unroll
    for (int q = 0; q < 4; q++) {
        int idx = t + 256 * q;
        int row = idx >> 3;
        int c   = idx & 7;
        const float* src = pred + (size_t)(rowA0 + row) * D_DIM + k0 + c * 4;
        uint32_t dst = aBase + row * 128 + ((c ^ (row & 7)) << 4);
        cp_async16(dst, src);
    }
    // B: 256 rows x 8 chunks = 2048 chunks, 8/thread
    #pragma unroll
    for (int q = 0; q < 8; q++) {
        int idx = t + 256 * q;
        int row = idx >> 3;
        int c   = idx & 7;
        const float* src = gt + (size_t)(rowB0 + row) * D_DIM + k0 + c * 4;
        uint32_t dst = bBase + row * 128 + ((c ^ (row & 7)) << 4);
        cp_async16(dst, src);
    }
}

__global__ __launch_bounds__(256)
void gemm_hinge_mma(const float* __restrict__ pred, const float* __restrict__ gt) {
    extern __shared__ char dyn[];
    __shared__ double redsm[8];

    const int t    = threadIdx.x;
    const int wid  = t >> 5;
    const int lane = t & 31;
    const int wm   = wid & 1;    // warp row (2)
    const int wn   = wid >> 1;   // warp col (4)
    const int tg   = lane >> 2;  // groupID 0..7
    const int rowA0 = blockIdx.y * TM;   // pred rows (i)
    const int rowB0 = blockIdx.x * TN;   // gt rows   (j)

    const uint32_t dyn_base = (smem_u32(dyn) + 1023u) & ~1023u;

    // ldmatrix per-thread geometry: tile = lane>>3, tile-row = lane&7.
    const int trow = lane & 7;
    const int tlLo = (lane >> 3) & 1;   // tile&1
    const int tlHi = (lane >> 4) & 1;   // tile>>1
    // A x4: tiles {rows+0,ch0},{rows+8,ch0},{rows+0,ch1},{rows+8,ch1}
    int arow[4], axor[4];
    #pragma unroll
    for (int mf = 0; mf < 4; mf++) {
        int r = wm * 64 + mf * 16 + tlLo * 8 + trow;
        arow[mf] = r * 128;
        axor[mf] = r & 7;
    }
    const int aCadd = tlHi;  // chunk add for A tiles
    // B x4 (nf pair p): tiles {n+0,ch0},{n+0,ch1},{n+8,ch0},{n+8,ch1}
    int brow[4], bxor[4];
    #pragma unroll
    for (int p = 0; p < 4; p++) {
        int r = wn * 64 + p * 16 + tlHi * 8 + trow;
        brow[p] = r * 128;
        bxor[p] = r & 7;
    }
    const int bCadd = tlLo;  // chunk add for B tiles

    float c[4][8][4];
    #pragma unroll
    for (int mf = 0; mf < 4; mf++)
        #pragma unroll
        for (int nf = 0; nf < 8; nf++)
            #pragma unroll
            for (int r = 0; r < 4; r++) c[mf][nf][r] = 0.0f;

    // Prologue: prefetch stages 0, 1.
    load_stage(dyn_base,               dyn_base + STAGE_A_BYTES,
               pred, gt, rowA0, rowB0, 0, t);
    cp_commit();
    load_stage(dyn_base + STAGE_BYTES, dyn_base + STAGE_BYTES + STAGE_A_BYTES,
               pred, gt, rowA0, rowB0, BKF, t);
    cp_commit();

    for (int it = 0; it < NKITERS; ++it) {
        const uint32_t aBase = dyn_base + (it % NSTAGE) * STAGE_BYTES;
        const uint32_t bBase = aBase + STAGE_A_BYTES;

        if (it < NKITERS - 1) cp_wait1(); else cp_wait0();
        __syncthreads();  // stage `it` visible to all; stage (it+2)%3 free

        if (it + 2 < NKITERS) {
            const uint32_t la = dyn_base + ((it + 2) % NSTAGE) * STAGE_BYTES;
            load_stage(la, la + STAGE_A_BYTES, pred, gt, rowA0, rowB0,
                       (it + 2) * BKF, t);
            cp_commit();
        }

        #pragma unroll
        for (int ks = 0; ks < 4; ks++) {
            uint32_t a[4][4];
            #pragma unroll
            for (int mf = 0; mf < 4; mf++) {
                int ch = 2 * ks + aCadd;
                ldsm4(a[mf], aBase + arow[mf] + ((ch ^ axor[mf]) << 4));
            }
            uint32_t b[4][4];  // b[p] = {b0(nf=2p), b1(nf=2p), b0(2p+1), b1(2p+1)}
            #pragma unroll
            for (int p = 0; p < 4; p++) {
                int ch = 2 * ks + bCadd;
                ldsm4(b[p], bBase + brow[p] + ((ch ^ bxor[p]) << 4));
            }
            #pragma unroll
            for (int mf = 0; mf < 4; mf++)
                #pragma unroll
                for (int nf = 0; nf < 8; nf++)
                    mma_tf32(c[mf][nf], a[mf], b[nf >> 1] + (nf & 1) * 2);
        }
    }

    // Hinge epilogue straight from register accumulators.
    double acc = 0.0;
    #pragma unroll
    for (int mf = 0; mf < 4; mf++) {
        int r0 = rowA0 + wm * 64 + mf * 16 + tg;
        float p0 = 1.0f - g_pos[r0];
        float p1 = 1.0f - g_pos[r0 + 8];
        #pragma unroll
        for (int nf = 0; nf < 8; nf++) {
            float v0 = c[mf][nf][0] + p0;
            float v1 = c[mf][nf][1] + p0;
            float v2 = c[mf][nf][2] + p1;
            float v3 = c[mf][nf][3] + p1;
            if (v0 > 0.0f) acc += (double)v0;
            if (v1 > 0.0f) acc += (double)v1;
            if (v2 > 0.0f) acc += (double)v2;
            if (v3 > 0.0f) acc += (double)v3;
        }
    }

    for (int o = 16; o > 0; o >>= 1)
        acc += __shfl_down_sync(0xffffffffu, acc, o);
    if (lane == 0) redsm[wid] = acc;
    __syncthreads();
    if (t == 0) {
        double tot = 0.0;
        #pragma unroll
        for (int w = 0; w < 8; w++) tot += redsm[w];
        atomicAdd(&g_glob_sum, tot);
    }
}

// ---------------------------------------------------------------------------
__global__ void finalize_kernel(float* __restrict__ out) {
    out[0] = (float)(g_glob_sum - g_local_sum / (double)L_DIM);
}

// ---------------------------------------------------------------------------
extern "C" void kernel_launch(void* const* d_in, const int* in_sizes, int n_in,
                              void* d_out, int out_size) {
    (void)in_sizes; (void)n_in; (void)out_size;
    const float* q_hat  = (const float*)d_in[0];
    const float* q_real = (const float*)d_in[1];
    const float* gt     = (const float*)d_in[2];  // encoded_gt   [B, D]
    const float* pred   = (const float*)d_in[3];  // encoded_pred [B, D]
    float* out = (float*)d_out;

    cudaFuncSetAttribute(gemm_hinge_mma,
                         cudaFuncAttributeMaxDynamicSharedMemorySize, DYN_SMEM);

    init_kernel<<<1, 1>>>();
    local_kernel<<<2048, 256>>>(q_hat, q_real);
    pos_kernel<<<B_DIM, 256>>>(pred, gt);
    dim3 grid(B_DIM / TN, B_DIM / TM);  // (16 j-tiles, 32 i-tiles)
    gemm_hinge_mma<<<grid, 256, DYN_SMEM>>>(pred, gt);
    finalize_kernel<<<1, 1>>>(out);
}